// round 2
// baseline (speedup 1.0000x reference)
#include <cuda_runtime.h>
#include <cuda_bf16.h>
#include <cstdint>

#define TSTEPS  512
#define BATCH   128
#define HID     512
#define NIN     256
#define GATES   2048
#define K0      768
#define K1      1024
#define NTILE   32
#define THREADS 256
#define NCTA    128

#define KP0     (K0 + 8)     // 776  (bank-padded W row, bf16 elems)
#define KP1     (K1 + 8)     // 1032

// SMEM layout (bytes)
#define W_OFF    0
#define W_BYTES  (NTILE * KP1 * 2)            // 66048
#define A0_OFF   (W_OFF + W_BYTES)            // 66048
#define A_BYTES  (BATCH * 144)                // 18432 (row stride 72 bf16 = 144B)
#define A1_OFF   (A0_OFF + A_BYTES)           // 84480
#define G_OFF    (A1_OFF + A_BYTES)           // 102912, gbuf [128][36] f32
#define G_BYTES  (BATCH * 36 * 4)             // 18432
#define SC_OFF   (G_OFF + G_BYTES)            // 121344, c state [128][8] f32
#define SC_BYTES (BATCH * 8 * 4)              // 4096
#define SB_OFF   (SC_OFF + SC_BYTES)          // 125440, bias [32] f32
#define SMEM_BYTES (SB_OFF + 128)             // 125568

// ------------------- device globals (no cudaMalloc allowed) -------------------
__device__ __nv_bfloat16 g_xT[(size_t)TSTEPS * BATCH * NIN];  // [t][b][i]
__device__ __nv_bfloat16 g_W0[(size_t)GATES * K0];            // [n'=4j+g][k], k=[x|h]
__device__ __nv_bfloat16 g_W1[(size_t)GATES * K1];            // [n'][k], k=[y0|h]
__device__ float g_b0[GATES];
__device__ float g_b1[GATES];
__device__ __nv_bfloat16 g_h0[2][BATCH * HID];                // double-buffered h, layer 0
__device__ __nv_bfloat16 g_h1[2][BATCH * HID];                // layer 1
__device__ float g_hfin[2 * BATCH * HID];                     // final h, fp32
__device__ unsigned g_bar_count;
__device__ volatile unsigned g_bar_epoch;

__device__ __forceinline__ float tanha(float x) {
    float r; asm("tanh.approx.f32 %0, %1;" : "=f"(r) : "f"(x)); return r;
}
__device__ __forceinline__ float sigm(float x) { return 0.5f * tanha(0.5f * x) + 0.5f; }

// ------------------------------- prep kernel ---------------------------------
// Packs weights bf16 gate-interleaved (n' = 4*j + gate), transposes x to
// [T][B][I] bf16, zeros the initial h buffers, resets the grid barrier.
__global__ void prep_kernel(const float* __restrict__ x,
                            const float* __restrict__ wih0, const float* __restrict__ whh0,
                            const float* __restrict__ b0,
                            const float* __restrict__ wih1, const float* __restrict__ whh1,
                            const float* __restrict__ b1) {
    const int64_t gtid = (int64_t)blockIdx.x * blockDim.x + threadIdx.x;
    const int64_t stride = (int64_t)gridDim.x * blockDim.x;
    if (gtid == 0) { g_bar_count = 0; g_bar_epoch = 0; }

    for (int64_t i = gtid; i < (int64_t)GATES * K0; i += stride) {
        int np = (int)(i / K0), k = (int)(i % K0);
        int j = np >> 2, gate = np & 3, n = gate * HID + j;
        float v = (k < NIN) ? wih0[(size_t)n * NIN + k] : whh0[(size_t)n * HID + (k - NIN)];
        g_W0[i] = __float2bfloat16(v);
    }
    for (int64_t i = gtid; i < (int64_t)GATES * K1; i += stride) {
        int np = (int)(i / K1), k = (int)(i % K1);
        int j = np >> 2, gate = np & 3, n = gate * HID + j;
        float v = (k < HID) ? wih1[(size_t)n * HID + k] : whh1[(size_t)n * HID + (k - HID)];
        g_W1[i] = __float2bfloat16(v);
    }
    for (int64_t i = gtid; i < GATES; i += stride) {
        int np = (int)i, j = np >> 2, gate = np & 3, n = gate * HID + j;
        g_b0[i] = b0[n]; g_b1[i] = b1[n];
    }
    // x [B,T,I] fp32 -> xT [T,B,I] bf16
    for (int64_t i = gtid; i < (int64_t)TSTEPS * BATCH * NIN; i += stride) {
        int t = (int)(i / (BATCH * NIN));
        int rem = (int)(i % (BATCH * NIN));
        int b = rem / NIN, d = rem % NIN;
        g_xT[i] = __float2bfloat16(x[((size_t)b * TSTEPS + t) * NIN + d]);
    }
    for (int64_t i = gtid; i < BATCH * HID; i += stride) {
        g_h0[0][i] = __float2bfloat16(0.f);
        g_h1[0][i] = __float2bfloat16(0.f);
    }
}

// ------------------------------ grid barrier ---------------------------------
__device__ __forceinline__ void gridbar(int s) {
    __threadfence();
    __syncthreads();
    if (threadIdx.x == 0) {
        unsigned target = (unsigned)(s + 1);
        unsigned arr = atomicAdd(&g_bar_count, 1u);
        if (arr == target * NCTA - 1u) {
            atomicExch((unsigned*)&g_bar_epoch, target);
        } else {
            while (g_bar_epoch < target) __nanosleep(32);
        }
    }
    __syncthreads();
}

// --------------------------- A-chunk loader (cp.async.cg) --------------------
// Loads a [128 rows x 64 bf16] chunk to SMEM (row stride 144B), L2-only.
__device__ __forceinline__ void load_chunk(uint32_t dst, const __nv_bfloat16* src,
                                           int strideElems) {
#pragma unroll
    for (int it = 0; it < 4; ++it) {
        int idx = threadIdx.x + it * THREADS;     // 0..1023
        int row = idx >> 3, q = idx & 7;
        const void* g = (const char*)(src + (size_t)row * strideElems) + q * 16;
        uint32_t d = dst + row * 144 + q * 16;
        asm volatile("cp.async.cg.shared.global [%0], [%1], 16;\n" :: "r"(d), "l"(g));
    }
}

// ------------------------- persistent wavefront LSTM -------------------------
// CTA 0..63  : layer 0, gate tile n0 = tile*32, K=768  (A = [x_t | h0])
// CTA 64..127: layer 1, K=1024 (A = [y0_t | h1]); phase s runs t=s (L0), t=s-1 (L1)
__global__ void __launch_bounds__(THREADS, 1) lstm_run() {
    extern __shared__ char smem[];
    const int tid = threadIdx.x, lane = tid & 31, warp = tid >> 5;
    const int wm = warp & 3, wn = warp >> 2;       // 4 M-warps x 2 N-warps
    const int layer = blockIdx.x >> 6;
    const int tile = blockIdx.x & 63;
    const int n0 = tile * NTILE, j0 = tile * 8;
    const int K = layer ? K1 : K0;
    const int Kp = layer ? KP1 : KP0;
    const int nch = K / 64;

    uint32_t sbase = (uint32_t)__cvta_generic_to_shared(smem);
    const uint32_t Wb = sbase + W_OFF;
    const uint32_t Ab0 = sbase + A0_OFF, Ab1 = sbase + A1_OFF;
    float* gbuf = (float*)(smem + G_OFF);
    float* sc = (float*)(smem + SC_OFF);
    float* sbias = (float*)(smem + SB_OFF);

    // Stationary weight slice -> SMEM (bank-padded rows)
    {
        const __nv_bfloat16* Wg = (layer ? g_W1 : g_W0) + (size_t)n0 * K;
        const int rowvec = K >> 3;
        for (int i = tid; i < NTILE * rowvec; i += THREADS) {
            int r = i / rowvec, q = i % rowvec;
            uint4 v = *(const uint4*)(Wg + (size_t)r * K + q * 8);
            *(uint4*)(smem + W_OFF + r * (Kp * 2) + q * 16) = v;
        }
        if (tid < NTILE) sbias[tid] = (layer ? g_b1 : g_b0)[n0 + tid];
        for (int i = tid; i < BATCH * 8; i += THREADS) sc[i] = 0.f;
    }
    __syncthreads();

    for (int s = 0; s <= TSTEPS; ++s) {
        const bool active = layer ? (s >= 1) : (s < TSTEPS);
        if (active) {
            const int t = layer ? (s - 1) : s;

            // chunk source resolver
            const __nv_bfloat16* xp = g_xT + (size_t)t * BATCH * NIN;
            const __nv_bfloat16* h0rd = g_h0[s & 1];
            const __nv_bfloat16* h1rd = g_h1[(s - 1) & 1];

            // prologue: chunk 0
            if (layer == 0) load_chunk(Ab0, xp, NIN);
            else            load_chunk(Ab0, h0rd, HID);
            asm volatile("cp.async.commit_group;\n");

            float acc[2][2][4] = {};
            for (int c = 0; c < nch; ++c) {
                if (c + 1 < nch) {
                    int cn = c + 1;
                    const __nv_bfloat16* p; int str;
                    if (layer == 0) {
                        if (cn < 4) { p = xp + cn * 64; str = NIN; }
                        else        { p = h0rd + (cn - 4) * 64; str = HID; }
                    } else {
                        if (cn < 8) { p = h0rd + cn * 64; str = HID; }
                        else        { p = h1rd + (cn - 8) * 64; str = HID; }
                    }
                    load_chunk((cn & 1) ? Ab1 : Ab0, p, str);
                }
                asm volatile("cp.async.commit_group;\n");
                asm volatile("cp.async.wait_group 1;\n");
                __syncthreads();

                const uint32_t A = (c & 1) ? Ab1 : Ab0;
                const int kb = c * 64;
#pragma unroll
                for (int kk = 0; kk < 4; ++kk) {
                    uint32_t a[2][4], bb[2][2];
                    const int colb = (kk * 16 + (lane & 3) * 2) * 2;
#pragma unroll
                    for (int i = 0; i < 2; ++i) {
                        uint32_t p = A + (wm * 32 + i * 16 + (lane >> 2)) * 144 + colb;
                        asm volatile("ld.shared.b32 %0,[%1];" : "=r"(a[i][0]) : "r"(p));
                        asm volatile("ld.shared.b32 %0,[%1];" : "=r"(a[i][1]) : "r"(p + 8 * 144));
                        asm volatile("ld.shared.b32 %0,[%1];" : "=r"(a[i][2]) : "r"(p + 16));
                        asm volatile("ld.shared.b32 %0,[%1];" : "=r"(a[i][3]) : "r"(p + 8 * 144 + 16));
                    }
#pragma unroll
                    for (int jn = 0; jn < 2; ++jn) {
                        int n = wn * 16 + jn * 8 + (lane >> 2);
                        uint32_t q = Wb + n * (Kp * 2) + (kb + kk * 16 + (lane & 3) * 2) * 2;
                        asm volatile("ld.shared.b32 %0,[%1];" : "=r"(bb[jn][0]) : "r"(q));
                        asm volatile("ld.shared.b32 %0,[%1];" : "=r"(bb[jn][1]) : "r"(q + 16));
                    }
#pragma unroll
                    for (int i = 0; i < 2; ++i)
#pragma unroll
                        for (int jn = 0; jn < 2; ++jn)
                            asm volatile(
                                "mma.sync.aligned.m16n8k16.row.col.f32.bf16.bf16.f32 "
                                "{%0,%1,%2,%3},{%4,%5,%6,%7},{%8,%9},{%0,%1,%2,%3};"
                                : "+f"(acc[i][jn][0]), "+f"(acc[i][jn][1]),
                                  "+f"(acc[i][jn][2]), "+f"(acc[i][jn][3])
                                : "r"(a[i][0]), "r"(a[i][1]), "r"(a[i][2]), "r"(a[i][3]),
                                  "r"(bb[jn][0]), "r"(bb[jn][1]));
                }
                __syncthreads();
            }

            // accumulators -> gbuf
#pragma unroll
            for (int i = 0; i < 2; ++i)
#pragma unroll
                for (int jn = 0; jn < 2; ++jn) {
                    int row = wm * 32 + i * 16 + (lane >> 2);
                    int col = wn * 16 + jn * 8 + (lane & 3) * 2;
                    float* gp = gbuf + row * 36 + col;
                    gp[0] = acc[i][jn][0]; gp[1] = acc[i][jn][1];
                    float* gp2 = gbuf + (row + 8) * 36 + col;
                    gp2[0] = acc[i][jn][2]; gp2[1] = acc[i][jn][3];
                }
            __syncthreads();

            // elementwise LSTM cell (thread -> (batch b, 4 hidden cols))
            {
                const int b = tid >> 1, half = tid & 1;
                const float* gb = gbuf + b * 36 + half * 16;
                float hv[4];
#pragma unroll
                for (int m = 0; m < 4; ++m) {
                    float gi = gb[4 * m + 0] + sbias[half * 16 + 4 * m + 0];
                    float gf = gb[4 * m + 1] + sbias[half * 16 + 4 * m + 1];
                    float gg = gb[4 * m + 2] + sbias[half * 16 + 4 * m + 2];
                    float go = gb[4 * m + 3] + sbias[half * 16 + 4 * m + 3];
                    float co = sc[b * 8 + half * 4 + m];
                    float cn = sigm(gf) * co + sigm(gi) * tanha(gg);
                    sc[b * 8 + half * 4 + m] = cn;
                    hv[m] = sigm(go) * tanha(cn);
                }
                __nv_bfloat16* hd = (layer ? g_h1[s & 1] : g_h0[(s + 1) & 1])
                                    + (size_t)b * HID + j0 + half * 4;
                __nv_bfloat162 p0 = __floats2bfloat162_rn(hv[0], hv[1]);
                __nv_bfloat162 p1 = __floats2bfloat162_rn(hv[2], hv[3]);
                uint2 u; u.x = *(uint32_t*)&p0; u.y = *(uint32_t*)&p1;
                *(uint2*)hd = u;
                if (t == TSTEPS - 1) {
                    float4 f; f.x = hv[0]; f.y = hv[1]; f.z = hv[2]; f.w = hv[3];
                    *(float4*)(g_hfin + (size_t)layer * BATCH * HID + b * HID + j0 + half * 4) = f;
                }
            }
        }
        gridbar(s);
    }
}

// ------------------------------- fc epilogue ---------------------------------
__global__ void fc_out_kernel(const float* __restrict__ fcw, const float* __restrict__ fcb,
                              float* __restrict__ out) {
    __shared__ float red[128];
    const int row = blockIdx.x;           // 0..255 = l*128 + b
    const float* h = g_hfin + (size_t)row * HID;
    float s = 0.f;
    for (int j = threadIdx.x; j < HID; j += 128) s += h[j] * fcw[j];
    red[threadIdx.x] = s;
    __syncthreads();
    for (int o = 64; o > 0; o >>= 1) {
        if (threadIdx.x < o) red[threadIdx.x] += red[threadIdx.x + o];
        __syncthreads();
    }
    if (threadIdx.x == 0) out[row] = red[0] + fcb[0];
}

// -------------------------------- launcher -----------------------------------
extern "C" void kernel_launch(void* const* d_in, const int* in_sizes, int n_in,
                              void* d_out, int out_size) {
    const float* x    = (const float*)d_in[0];
    const float* wih0 = (const float*)d_in[1];
    const float* whh0 = (const float*)d_in[2];
    const float* b0   = (const float*)d_in[3];
    const float* wih1 = (const float*)d_in[4];
    const float* whh1 = (const float*)d_in[5];
    const float* b1   = (const float*)d_in[6];
    const float* fcw  = (const float*)d_in[7];
    const float* fcb  = (const float*)d_in[8];

    cudaFuncSetAttribute(lstm_run, cudaFuncAttributeMaxDynamicSharedMemorySize, SMEM_BYTES);

    prep_kernel<<<2048, 256>>>(x, wih0, whh0, b0, wih1, whh1, b1);
    lstm_run<<<NCTA, THREADS, SMEM_BYTES>>>();
    fc_out_kernel<<<256, 128>>>(fcw, fcb, (float*)d_out);
}

// round 3
// speedup vs baseline: 1.4378x; 1.4378x over previous
#include <cuda_runtime.h>
#include <cuda_bf16.h>
#include <cstdint>

#define TSTEPS  512
#define BATCH   128
#define HID     512
#define NIN     256
#define GATES   2048
#define K0      768
#define K1      1024
#define NTILE   32
#define THREADS 256
#define NCTA    128
#define NCH0    12          // K0/64
#define NCH1    16          // K1/64
#define CHE     8192        // elems per chunk block (128 rows x 64 bf16)
#define CHB     16384       // bytes per chunk block
#define NSTAGE  4

// SMEM layout (bytes)
#define W_OFF    0
#define A_OFF    65536                         // 4 stages x 16KB
#define G_OFF    (A_OFF + NSTAGE * CHB)        // 131072  gbuf [128][36] f32
#define SC_OFF   (G_OFF + BATCH * 36 * 4)      // 149504  c state [128][8] f32
#define SB_OFF   (SC_OFF + BATCH * 8 * 4)      // 153600  bias [32] f32
#define MB_OFF   (SB_OFF + 128)                // 153728  4 mbarriers
#define SMEM_BYTES (MB_OFF + 64)               // 153792

// ------------------- device globals (no cudaMalloc allowed) -------------------
// All hot arrays are chunk-major and SW128-swizzled (8-row x 128B atoms) so that
// cp.async.bulk copies them verbatim into SMEM and ldmatrix reads conflict-free.
__device__ __nv_bfloat16 g_xT[(size_t)TSTEPS * 4 * CHE];        // [t][c4][128][64]
__device__ __nv_bfloat16 g_W0p[(size_t)64 * NCH0 * NTILE * 64]; // [tile][c][32][64]
__device__ __nv_bfloat16 g_W1p[(size_t)64 * NCH1 * NTILE * 64];
__device__ float g_b0[GATES];                                   // n' = 4j+gate order
__device__ float g_b1[GATES];
__device__ __nv_bfloat16 g_h0[2][8 * CHE];                      // [buf][c8][128][64]
__device__ __nv_bfloat16 g_h1[2][8 * CHE];
__device__ float g_hfin[2 * BATCH * HID];
__device__ unsigned g_bar_count;
__device__ volatile unsigned g_bar_epoch;

__device__ __forceinline__ float tanha(float x) {
    float r; asm("tanh.approx.f32 %0, %1;" : "=f"(r) : "f"(x)); return r;
}
__device__ __forceinline__ float sigm(float x) { return 0.5f * tanha(0.5f * x) + 0.5f; }

// ------------------------------- prep kernel ---------------------------------
__global__ void prep_kernel(const float* __restrict__ x,
                            const float* __restrict__ wih0, const float* __restrict__ whh0,
                            const float* __restrict__ b0,
                            const float* __restrict__ wih1, const float* __restrict__ whh1,
                            const float* __restrict__ b1) {
    const int64_t gtid = (int64_t)blockIdx.x * blockDim.x + threadIdx.x;
    const int64_t stride = (int64_t)gridDim.x * blockDim.x;
    if (gtid == 0) { g_bar_count = 0; g_bar_epoch = 0; }

    // W0 packed: iterate destination, unswizzle (XOR is an involution)
    for (int64_t i = gtid; i < (int64_t)64 * NCH0 * NTILE * 64; i += stride) {
        int tile = (int)(i / (NCH0 * NTILE * 64));
        int rem = (int)(i % (NCH0 * NTILE * 64));
        int c = rem / (NTILE * 64);
        int r = (rem % (NTILE * 64)) / 64;      // n-row within tile (0..31)
        int ce = rem % 64;                       // swizzled elem col
        int col = (((ce * 2) ^ ((r & 7) << 4)) >> 1);
        int k = c * 64 + col;
        int np = tile * NTILE + r, j = np >> 2, gate = np & 3, n = gate * HID + j;
        float v = (k < NIN) ? wih0[(size_t)n * NIN + k] : whh0[(size_t)n * HID + (k - NIN)];
        g_W0p[i] = __float2bfloat16(v);
    }
    for (int64_t i = gtid; i < (int64_t)64 * NCH1 * NTILE * 64; i += stride) {
        int tile = (int)(i / (NCH1 * NTILE * 64));
        int rem = (int)(i % (NCH1 * NTILE * 64));
        int c = rem / (NTILE * 64);
        int r = (rem % (NTILE * 64)) / 64;
        int ce = rem % 64;
        int col = (((ce * 2) ^ ((r & 7) << 4)) >> 1);
        int k = c * 64 + col;
        int np = tile * NTILE + r, j = np >> 2, gate = np & 3, n = gate * HID + j;
        float v = (k < HID) ? wih1[(size_t)n * HID + k] : whh1[(size_t)n * HID + (k - HID)];
        g_W1p[i] = __float2bfloat16(v);
    }
    for (int64_t i = gtid; i < GATES; i += stride) {
        int np = (int)i, j = np >> 2, gate = np & 3, n = gate * HID + j;
        g_b0[i] = b0[n]; g_b1[i] = b1[n];
    }
    // x [B,T,I] -> chunked swizzled [t][c][b][64]
    for (int64_t i = gtid; i < (int64_t)TSTEPS * 4 * CHE; i += stride) {
        int t = (int)(i / (4 * CHE));
        int rem = (int)(i % (4 * CHE));
        int c = rem / CHE;
        int b = (rem % CHE) / 64;
        int ce = rem % 64;
        int col = (((ce * 2) ^ ((b & 7) << 4)) >> 1);
        int d = c * 64 + col;
        g_xT[i] = __float2bfloat16(x[((size_t)b * TSTEPS + t) * NIN + d]);
    }
    for (int64_t i = gtid; i < 8 * CHE; i += stride) {
        g_h0[0][i] = __float2bfloat16(0.f);
        g_h1[0][i] = __float2bfloat16(0.f);
    }
}

// ------------------------------ grid barrier ---------------------------------
__device__ __forceinline__ void gridbar(int s) {
    __threadfence();
    __syncthreads();
    if (threadIdx.x == 0) {
        unsigned target = (unsigned)(s + 1);
        unsigned arr = atomicAdd(&g_bar_count, 1u);
        if (arr == target * NCTA - 1u) {
            atomicExch((unsigned*)&g_bar_epoch, target);
        } else {
            while (g_bar_epoch < target) __nanosleep(32);
        }
    }
    __syncthreads();
}

// ------------------------- persistent wavefront LSTM -------------------------
__global__ void __launch_bounds__(THREADS, 1) lstm_run() {
    extern __shared__ char smem[];
    const int tid = threadIdx.x, lane = tid & 31, warp = tid >> 5;
    const int wm = warp & 3, wn = warp >> 2;     // 4 M-warps x 2 N-warps
    const int layer = blockIdx.x >> 6;
    const int tile = blockIdx.x & 63;
    const int n0 = tile * NTILE, j0 = tile * 8;
    const int nch = layer ? NCH1 : NCH0;

    uint32_t sbase = (uint32_t)__cvta_generic_to_shared(smem);
    const uint32_t Wb = sbase + W_OFF;
    const uint32_t Ab = sbase + A_OFF;
    const uint32_t Mb = sbase + MB_OFF;
    float* gbuf = (float*)(smem + G_OFF);
    float* sc = (float*)(smem + SC_OFF);
    float* sbias = (float*)(smem + SB_OFF);

    // stationary W slice (already swizzled): straight 16B copy
    {
        const __nv_bfloat16* Wg = (layer ? g_W1p : g_W0p) + (size_t)tile * nch * NTILE * 64;
        const int nvec = nch * NTILE * 64 / 8;
        for (int i = tid; i < nvec; i += THREADS)
            *(uint4*)(smem + W_OFF + i * 16) = *(const uint4*)(Wg + (size_t)i * 8);
        if (tid < NTILE) sbias[tid] = (layer ? g_b1 : g_b0)[n0 + tid];
        for (int i = tid; i < BATCH * 8; i += THREADS) sc[i] = 0.f;
        if (tid == 0) {
#pragma unroll
            for (int st = 0; st < NSTAGE; ++st)
                asm volatile("mbarrier.init.shared.b64 [%0], 1;" :: "r"(Mb + st * 8) : "memory");
        }
        asm volatile("fence.proxy.async.shared::cta;" ::: "memory");
    }
    __syncthreads();

    unsigned phase_bits = 0;

    for (int s = 0; s <= TSTEPS; ++s) {
        const bool active = layer ? (s >= 1) : (s < TSTEPS);
        if (active) {
            const int t = layer ? (s - 1) : s;
            const __nv_bfloat16* xp = g_xT + (size_t)t * 4 * CHE;
            const __nv_bfloat16* h0rd = g_h0[s & 1];
            const __nv_bfloat16* h1rd = g_h1[(s - 1) & 1];

            // bulk-copy issue helper (inlined): one UBLKCP of 16KB per chunk
            auto issue = [&](int cc, int st) {
                const __nv_bfloat16* srcp;
                if (layer == 0) srcp = (cc < 4) ? xp + (size_t)cc * CHE
                                                : h0rd + (size_t)(cc - 4) * CHE;
                else            srcp = (cc < 8) ? h0rd + (size_t)cc * CHE
                                                : h1rd + (size_t)(cc - 8) * CHE;
                uint32_t bar = Mb + st * 8;
                uint32_t dst = Ab + st * CHB;
                asm volatile("mbarrier.arrive.expect_tx.shared.b64 _, [%0], %1;"
                             :: "r"(bar), "r"((unsigned)CHB) : "memory");
                asm volatile("cp.async.bulk.shared::cta.global.mbarrier::complete_tx::bytes "
                             "[%0], [%1], %2, [%3];"
                             :: "r"(dst), "l"(srcp), "r"((unsigned)CHB), "r"(bar) : "memory");
            };

            if (tid == 0)
                for (int p = 0; p < NSTAGE && p < nch; ++p) issue(p, p);

            float acc[2][2][4] = {};
            for (int c = 0; c < nch; ++c) {
                const int st = c & (NSTAGE - 1);
                // wait for stage
                {
                    uint32_t bar = Mb + st * 8;
                    uint32_t ph = (phase_bits >> st) & 1u;
                    uint32_t done;
                    asm volatile("{\n .reg .pred p;\n"
                                 " mbarrier.try_wait.parity.shared.b64 p, [%1], %2;\n"
                                 " selp.b32 %0, 1, 0, p;\n}"
                                 : "=r"(done) : "r"(bar), "r"(ph) : "memory");
                    while (!done) {
                        asm volatile("{\n .reg .pred p;\n"
                                     " mbarrier.try_wait.parity.shared.b64 p, [%1], %2;\n"
                                     " selp.b32 %0, 1, 0, p;\n}"
                                     : "=r"(done) : "r"(bar), "r"(ph) : "memory");
                    }
                    phase_bits ^= (1u << st);
                }

                const uint32_t A = Ab + st * CHB;
                const uint32_t Wc = Wb + c * (NTILE * 128);
#pragma unroll
                for (int kk = 0; kk < 4; ++kk) {
                    uint32_t a[2][4], b4[4];
                    // A fragments: 2x ldmatrix.x4 (m16k16 each)
#pragma unroll
                    for (int i = 0; i < 2; ++i) {
                        int sub = lane >> 3;
                        int row = wm * 32 + i * 16 + (lane & 7) + (sub & 1) * 8;
                        int unit = kk * 2 + (sub >> 1);
                        uint32_t ad = A + row * 128 + ((unit * 16) ^ ((row & 7) << 4));
                        asm volatile("ldmatrix.sync.aligned.m8n8.x4.shared.b16 "
                                     "{%0,%1,%2,%3}, [%4];"
                                     : "=r"(a[i][0]), "=r"(a[i][1]),
                                       "=r"(a[i][2]), "=r"(a[i][3]) : "r"(ad));
                    }
                    // B fragments: 1x ldmatrix.x4 covers n16k16 (both jn tiles)
                    {
                        int row = wn * 16 + (lane & 7) + ((lane >> 3) & 1) * 8;
                        int unit = kk * 2 + (lane >> 4);
                        uint32_t bd = Wc + row * 128 + ((unit * 16) ^ ((row & 7) << 4));
                        asm volatile("ldmatrix.sync.aligned.m8n8.x4.shared.b16 "
                                     "{%0,%1,%2,%3}, [%4];"
                                     : "=r"(b4[0]), "=r"(b4[1]), "=r"(b4[2]), "=r"(b4[3])
                                     : "r"(bd));
                    }
                    // jn=0 uses {b4[0], b4[2]}; jn=1 uses {b4[1], b4[3]}
#pragma unroll
                    for (int i = 0; i < 2; ++i) {
                        asm volatile(
                            "mma.sync.aligned.m16n8k16.row.col.f32.bf16.bf16.f32 "
                            "{%0,%1,%2,%3},{%4,%5,%6,%7},{%8,%9},{%0,%1,%2,%3};"
                            : "+f"(acc[i][0][0]), "+f"(acc[i][0][1]),
                              "+f"(acc[i][0][2]), "+f"(acc[i][0][3])
                            : "r"(a[i][0]), "r"(a[i][1]), "r"(a[i][2]), "r"(a[i][3]),
                              "r"(b4[0]), "r"(b4[2]));
                        asm volatile(
                            "mma.sync.aligned.m16n8k16.row.col.f32.bf16.bf16.f32 "
                            "{%0,%1,%2,%3},{%4,%5,%6,%7},{%8,%9},{%0,%1,%2,%3};"
                            : "+f"(acc[i][1][0]), "+f"(acc[i][1][1]),
                              "+f"(acc[i][1][2]), "+f"(acc[i][1][3])
                            : "r"(a[i][0]), "r"(a[i][1]), "r"(a[i][2]), "r"(a[i][3]),
                              "r"(b4[1]), "r"(b4[3]));
                    }
                }
                __syncthreads();               // all warps done reading this stage
                if (tid == 0 && c + NSTAGE < nch) issue(c + NSTAGE, st);
            }

            // accumulators -> gbuf
#pragma unroll
            for (int i = 0; i < 2; ++i)
#pragma unroll
                for (int jn = 0; jn < 2; ++jn) {
                    int row = wm * 32 + i * 16 + (lane >> 2);
                    int col = wn * 16 + jn * 8 + (lane & 3) * 2;
                    float* gp = gbuf + row * 36 + col;
                    gp[0] = acc[i][jn][0]; gp[1] = acc[i][jn][1];
                    float* gp2 = gbuf + (row + 8) * 36 + col;
                    gp2[0] = acc[i][jn][2]; gp2[1] = acc[i][jn][3];
                }
            __syncthreads();

            // elementwise LSTM cell
            {
                const int b = tid >> 1, half = tid & 1;
                const float* gb = gbuf + b * 36 + half * 16;
                float hv[4];
#pragma unroll
                for (int m = 0; m < 4; ++m) {
                    float gi = gb[4 * m + 0] + sbias[half * 16 + 4 * m + 0];
                    float gf = gb[4 * m + 1] + sbias[half * 16 + 4 * m + 1];
                    float gg = gb[4 * m + 2] + sbias[half * 16 + 4 * m + 2];
                    float go = gb[4 * m + 3] + sbias[half * 16 + 4 * m + 3];
                    float co = sc[b * 8 + half * 4 + m];
                    float cn = sigm(gf) * co + sigm(gi) * tanha(gg);
                    sc[b * 8 + half * 4 + m] = cn;
                    hv[m] = sigm(go) * tanha(cn);
                }
                // chunked + swizzled h store
                __nv_bfloat16* hbase = layer ? g_h1[s & 1] : g_h0[(s + 1) & 1];
                int ch = j0 >> 6;
                int colbyte = ((((j0 & 63) + half * 4) * 2)) ^ ((b & 7) << 4);
                __nv_bfloat16* hd = hbase + ((size_t)ch * 128 + b) * 64 + (colbyte >> 1);
                __nv_bfloat162 p0 = __floats2bfloat162_rn(hv[0], hv[1]);
                __nv_bfloat162 p1 = __floats2bfloat162_rn(hv[2], hv[3]);
                uint2 u; u.x = *(uint32_t*)&p0; u.y = *(uint32_t*)&p1;
                *(uint2*)hd = u;
                if (t == TSTEPS - 1) {
                    float4 f; f.x = hv[0]; f.y = hv[1]; f.z = hv[2]; f.w = hv[3];
                    *(float4*)(g_hfin + (size_t)layer * BATCH * HID + b * HID + j0 + half * 4) = f;
                }
            }
        }
        gridbar(s);
    }
}

// ------------------------------- fc epilogue ---------------------------------
__global__ void fc_out_kernel(const float* __restrict__ fcw, const float* __restrict__ fcb,
                              float* __restrict__ out) {
    __shared__ float red[128];
    const int row = blockIdx.x;           // 0..255 = l*128 + b
    const float* h = g_hfin + (size_t)row * HID;
    float s = 0.f;
    for (int j = threadIdx.x; j < HID; j += 128) s += h[j] * fcw[j];
    red[threadIdx.x] = s;
    __syncthreads();
    for (int o = 64; o > 0; o >>= 1) {
        if (threadIdx.x < o) red[threadIdx.x] += red[threadIdx.x + o];
        __syncthreads();
    }
    if (threadIdx.x == 0) out[row] = red[0] + fcb[0];
}

// -------------------------------- launcher -----------------------------------
extern "C" void kernel_launch(void* const* d_in, const int* in_sizes, int n_in,
                              void* d_out, int out_size) {
    const float* x    = (const float*)d_in[0];
    const float* wih0 = (const float*)d_in[1];
    const float* whh0 = (const float*)d_in[2];
    const float* b0   = (const float*)d_in[3];
    const float* wih1 = (const float*)d_in[4];
    const float* whh1 = (const float*)d_in[5];
    const float* b1   = (const float*)d_in[6];
    const float* fcw  = (const float*)d_in[7];
    const float* fcb  = (const float*)d_in[8];

    cudaFuncSetAttribute(lstm_run, cudaFuncAttributeMaxDynamicSharedMemorySize, SMEM_BYTES);

    prep_kernel<<<2048, 256>>>(x, wih0, whh0, b0, wih1, whh1, b1);
    lstm_run<<<NCTA, THREADS, SMEM_BYTES>>>();
    fc_out_kernel<<<256, 128>>>(fcw, fcb, (float*)d_out);
}